// round 12
// baseline (speedup 1.0000x reference)
#include <cuda_runtime.h>
#include <cuda_bf16.h>
#include <cstdint>

#define INV_T   (1.0f/0.07f)
#define N_ROWS  512
#define D_IN    2048
#define DIM     128
#define KNEG    65536
#define NG      4

// ================= persistent device scratch =================
__device__ float g_part[8 * N_ROWS * DIM];
__device__ float g_q[N_ROWS * DIM];          // normalized q * 1/T, tf32-rounded
__device__ int   g_rows[NG * N_ROWS];
__device__ int   g_cnt[NG];

// ================= init =================
__global__ void init_kernel(float* __restrict__ out, long long out_size) {
    int t = threadIdx.x;
    if (t < NG) g_cnt[t] = 0;
    long long base = (long long)N_ROWS * (KNEG + 1);
    for (long long i = base + t; i < out_size; i += blockDim.x)
        out[i] = 0.0f;
}

// ================= projections (split-K partials) =================
__global__ void __launch_bounds__(256) proj_kernel(
    const float* __restrict__ im_q, const float* __restrict__ im_k,
    const float* __restrict__ W_q,  const float* __restrict__ W_k) {
    const int z  = blockIdx.z;
    const int ks = blockIdx.y;
    const int n0 = blockIdx.x * 16;
    const float* __restrict__ A = z ? im_k : im_q;
    const float* __restrict__ W = z ? W_k  : W_q;

    __shared__ float As[16][32];
    __shared__ float Bs[32][128];

    float acc[2][4] = {{0.f,0.f,0.f,0.f},{0.f,0.f,0.f,0.f}};
    const int t  = threadIdx.x;
    const int r0 = (t >> 5) << 1;
    const int c0 = (t & 31) << 2;
    const int kbeg = ks * 512;

    for (int kb = 0; kb < 512; kb += 32) {
        const int kbase = kbeg + kb;
        {
            int idx = t;
            #pragma unroll
            for (int i = 0; i < 2; ++i) {
                int r = idx >> 5, c = idx & 31;
                As[r][c] = A[(size_t)(n0 + r) * D_IN + kbase + c];
                idx += 256;
            }
        }
        #pragma unroll
        for (int i = 0; i < 16; ++i) {
            int idx = t + i * 256;
            int r = idx >> 7, c = idx & 127;
            Bs[r][c] = W[(size_t)(kbase + r) * DIM + c];
        }
        __syncthreads();
        #pragma unroll
        for (int kc = 0; kc < 32; ++kc) {
            float a0 = As[r0][kc], a1 = As[r0 + 1][kc];
            float4 b = *(const float4*)&Bs[kc][c0];
            acc[0][0] += a0 * b.x; acc[0][1] += a0 * b.y;
            acc[0][2] += a0 * b.z; acc[0][3] += a0 * b.w;
            acc[1][0] += a1 * b.x; acc[1][1] += a1 * b.y;
            acc[1][2] += a1 * b.z; acc[1][3] += a1 * b.w;
        }
        __syncthreads();
    }
    float* P = g_part + ((size_t)(z * 4 + ks) * N_ROWS + n0) * DIM;
    #pragma unroll
    for (int rr = 0; rr < 2; ++rr)
        #pragma unroll
        for (int cc = 0; cc < 4; ++cc)
            P[(size_t)(r0 + rr) * DIM + c0 + cc] = acc[rr][cc];
}

// ================= norm + l_pos + routing =================
__device__ __forceinline__ float block_reduce_128(float v, volatile float* sbuf) {
    #pragma unroll
    for (int o = 16; o > 0; o >>= 1)
        v += __shfl_xor_sync(0xffffffffu, v, o);
    __syncthreads();
    if ((threadIdx.x & 31) == 0) sbuf[threadIdx.x >> 5] = v;
    __syncthreads();
    return sbuf[0] + sbuf[1] + sbuf[2] + sbuf[3];
}

__global__ void __launch_bounds__(128) norm_kernel(const int* __restrict__ label,
                                                   float* __restrict__ out) {
    const int n = blockIdx.x;
    const int j = threadIdx.x;
    __shared__ float sbuf[4];

    float qv = 0.f, kv = 0.f;
    #pragma unroll
    for (int s = 0; s < 4; ++s) {
        qv += g_part[((size_t)s       * N_ROWS + n) * DIM + j];
        kv += g_part[((size_t)(4 + s) * N_ROWS + n) * DIM + j];
    }
    float sq = block_reduce_128(qv * qv, sbuf);
    float sk = block_reduce_128(kv * kv, sbuf);
    float qn = qv / fmaxf(sqrtf(sq), 1e-12f);
    float kn = kv / fmaxf(sqrtf(sk), 1e-12f);
    float lp = block_reduce_128(qn * kn, sbuf);

    float qscaled = qn * INV_T;
    uint32_t qt;
    asm("cvt.rna.tf32.f32 %0, %1;" : "=r"(qt) : "f"(qscaled));
    g_q[(size_t)n * DIM + j] = __uint_as_float(qt);

    if (j == 0) {
        out[(size_t)n * (KNEG + 1)] = lp * INV_T;
        int lab = label[n];
        int gq = ((lab - 1) % NG + NG) % NG;
        int p = atomicAdd(&g_cnt[gq], 1);
        g_rows[gq * N_ROWS + p] = n;
    }
}

// ================= l_neg: tf32 mma.sync, 64x64 warp tile, 256-col CTA tile ==
// CTA: 128 rows x 256 cols, 8 warps (2 m x 4 n), contraction over all 128 feats.
// SMEM: rowidx + A[128][132] + ring 3 x chunk[16][264]
#define OFF_ROWIDX 0
#define OFF_A      1024
#define PA         132
#define OFF_B      (OFF_A + 128 * PA * 4)          // 68608
#define PB         264
#define CHUNK_C    16
#define RING       3
#define CHUNK_BYTES (CHUNK_C * PB * 4)             // 16896
#define SMEM_LNEG  (OFF_B + RING * CHUNK_BYTES)    // 119296
#define NCHUNK     (DIM / CHUNK_C)                 // 8

__device__ __forceinline__ uint32_t smem_u32(const void* p) {
    uint32_t a;
    asm("{ .reg .u64 t; cvta.to.shared.u64 t, %1; cvt.u32.u64 %0, t; }" : "=r"(a) : "l"(p));
    return a;
}
__device__ __forceinline__ void cpasync16(uint32_t dst, const void* src) {
    asm volatile("cp.async.cg.shared.global [%0], [%1], 16;" :: "r"(dst), "l"(src));
}
__device__ __forceinline__ void mma_tf32(float* c, const uint32_t* a, const uint32_t* b) {
    asm volatile("mma.sync.aligned.m16n8k8.row.col.f32.tf32.tf32.f32 "
        "{%0,%1,%2,%3}, {%4,%5,%6,%7}, {%8,%9}, {%0,%1,%2,%3};"
        : "+f"(c[0]),"+f"(c[1]),"+f"(c[2]),"+f"(c[3])
        : "r"(a[0]),"r"(a[1]),"r"(a[2]),"r"(a[3]), "r"(b[0]),"r"(b[1]));
}

// issue cp.async for chunk cc (16 feats x 256 cols) into ring slot cc%3
__device__ __forceinline__ void issue_chunk(uint32_t sbase, const float* qgrp,
                                            int k0, int cc, int tid) {
    uint32_t dst = sbase + OFF_B + (uint32_t)(cc % RING) * CHUNK_BYTES;
    #pragma unroll
    for (int h = 0; h < 4; ++h) {
        int s   = tid + h * 256;           // 0..1023
        int r   = s >> 6;                  // chunk row 0..15
        int seg = s & 63;                  // 16B segment
        cpasync16(dst + (uint32_t)(r * (PB * 4) + seg * 16),
                  qgrp + (size_t)(cc * CHUNK_C + r) * KNEG + k0 + seg * 4);
    }
    asm volatile("cp.async.commit_group;");
}

__global__ void __launch_bounds__(256, 1) lneg_kernel(const float* __restrict__ queues,
                                                      float* __restrict__ out) {
    const int g   = blockIdx.y;
    const int m0  = blockIdx.z * 128;
    const int cnt = g_cnt[g];
    if (m0 >= cnt) return;

    extern __shared__ char smem[];
    const uint32_t sbase = smem_u32(smem);
    int* rowidx = (int*)(smem + OFF_ROWIDX);
    float* As   = (float*)(smem + OFF_A);

    const int tid  = threadIdx.x;
    const int w    = tid >> 5;
    const int lane = tid & 31;
    const float* qgrp = queues + (size_t)g * DIM * KNEG;
    const int k0 = blockIdx.x * 256;

    // prologue: 2 chunks in flight
    issue_chunk(sbase, qgrp, k0, 0, tid);
    issue_chunk(sbase, qgrp, k0, 1, tid);

    // rowidx + A fill (threads 0..127, one gathered q row each)
    if (tid < 128) {
        int r = m0 + tid;
        int myrow = (r < cnt) ? g_rows[g * N_ROWS + r] : -1;
        rowidx[tid] = myrow;
        float* arow = As + tid * PA;
        if (myrow >= 0) {
            const float4* src = (const float4*)(g_q + (size_t)myrow * DIM);
            #pragma unroll
            for (int i = 0; i < 32; ++i)
                *(float4*)(arow + i * 4) = src[i];
        } else {
            #pragma unroll
            for (int i = 0; i < 32; ++i)
                *(float4*)(arow + i * 4) = make_float4(0.f, 0.f, 0.f, 0.f);
        }
    }

    const int warp_m  = w >> 2;             // 0..1  -> 64 rows
    const int warp_n  = w & 3;              // 0..3  -> 64 cols
    const int m_base  = warp_m * 64;
    const int n_basew = warp_n * 64;
    const bool active = (m0 + m_base) < cnt;

    const int arow0 = m_base + (lane >> 2);
    const int acol0 = lane & 3;
    const int bn0   = n_basew + (lane >> 2);
    const int bk0   = lane & 3;

    float acc[4][8][4];
    #pragma unroll
    for (int mi = 0; mi < 4; ++mi)
        #pragma unroll
        for (int ni = 0; ni < 8; ++ni)
            #pragma unroll
            for (int e = 0; e < 4; ++e) acc[mi][ni][e] = 0.f;

    for (int cc = 0; cc < NCHUNK; ++cc) {
        // pending groups at top: chunks [cc .. min(cc+1, NCHUNK-1)]
        if (cc + 1 < NCHUNK) asm volatile("cp.async.wait_group 1;");
        else                 asm volatile("cp.async.wait_group 0;");
        __syncthreads();   // chunk cc visible; prior slot reads done

        if (cc + 2 < NCHUNK)
            issue_chunk(sbase, qgrp, k0, cc + 2, tid);

        if (active) {
            const float* chunk = (const float*)(smem + OFF_B +
                                 (uint32_t)(cc % RING) * CHUNK_BYTES);
            const int cbase = cc * CHUNK_C;

            #pragma unroll
            for (int ks2 = 0; ks2 < 2; ++ks2) {
                const int kloc = ks2 * 8;

                uint32_t a[4][4];
                #pragma unroll
                for (int mi = 0; mi < 4; ++mi) {
                    const float* ap = As + (arow0 + mi * 16) * PA + cbase + kloc + acol0;
                    a[mi][0] = __float_as_uint(ap[0]);
                    a[mi][1] = __float_as_uint(ap[8 * PA]);
                    a[mi][2] = __float_as_uint(ap[4]);
                    a[mi][3] = __float_as_uint(ap[8 * PA + 4]);
                }
                uint32_t b[8][2];
                const float* bp = chunk + (kloc + bk0) * PB + bn0;
                #pragma unroll
                for (int ni = 0; ni < 8; ++ni) {
                    b[ni][0] = __float_as_uint(bp[ni * 8]);
                    b[ni][1] = __float_as_uint(bp[4 * PB + ni * 8]);
                }
                #pragma unroll
                for (int ni = 0; ni < 8; ++ni)
                    #pragma unroll
                    for (int mi = 0; mi < 4; ++mi)
                        mma_tf32(acc[mi][ni], a[mi], b[ni]);
            }
        }
    }

    // single epilogue per CTA: scalar stores (col base 1 + k0 is odd)
    if (active) {
        #pragma unroll
        for (int mi = 0; mi < 4; ++mi) {
            int rlo = m_base + mi * 16 + (lane >> 2);
            int n0r = rowidx[rlo];
            int n1r = rowidx[rlo + 8];
            #pragma unroll
            for (int ni = 0; ni < 8; ++ni) {
                size_t col = (size_t)(1 + k0 + n_basew + ni * 8 + (lane & 3) * 2);
                if (n0r >= 0) {
                    float* p0 = out + (size_t)n0r * (KNEG + 1) + col;
                    p0[0] = acc[mi][ni][0];
                    p0[1] = acc[mi][ni][1];
                }
                if (n1r >= 0) {
                    float* p1 = out + (size_t)n1r * (KNEG + 1) + col;
                    p1[0] = acc[mi][ni][2];
                    p1[1] = acc[mi][ni][3];
                }
            }
        }
    }
}

// ================= launch =================
extern "C" void kernel_launch(void* const* d_in, const int* in_sizes, int n_in,
                              void* d_out, int out_size) {
    const float* im_q   = (const float*)d_in[0];
    const float* im_k   = (const float*)d_in[1];
    const float* W_q    = (const float*)d_in[2];
    const float* W_k    = (const float*)d_in[3];
    const float* queues = (const float*)d_in[4];
    const int*   label  = (const int*)d_in[5];
    float* out = (float*)d_out;

    cudaFuncSetAttribute(lneg_kernel, cudaFuncAttributeMaxDynamicSharedMemorySize, SMEM_LNEG);

    init_kernel<<<1, 256>>>(out, (long long)out_size);
    proj_kernel<<<dim3(32, 4, 2), 256>>>(im_q, im_k, W_q, W_k);
    norm_kernel<<<N_ROWS, 128>>>(label, out);
    lneg_kernel<<<dim3(KNEG / 256, NG, 4), 256, SMEM_LNEG>>>(queues, out);
}

// round 16
// speedup vs baseline: 1.7214x; 1.7214x over previous
#include <cuda_runtime.h>
#include <cuda_bf16.h>
#include <cstdint>

#define INV_T   (1.0f/0.07f)
#define N_ROWS  512
#define D_IN    2048
#define DIM     128
#define KNEG    65536
#define NG      4
#define KT      4            // k-tiles (128 cols) per CTA

// ================= persistent device scratch =================
__device__ float g_part[8 * N_ROWS * DIM];
__device__ float g_q[N_ROWS * DIM];          // normalized q * 1/T, tf32-rounded
__device__ int   g_rows[NG * N_ROWS];
__device__ int   g_cnt[NG];

// ================= init =================
__global__ void init_kernel(float* __restrict__ out, long long out_size) {
    int t = threadIdx.x;
    if (t < NG) g_cnt[t] = 0;
    long long base = (long long)N_ROWS * (KNEG + 1);
    for (long long i = base + t; i < out_size; i += blockDim.x)
        out[i] = 0.0f;
}

// ================= projections (split-K partials) =================
__global__ void __launch_bounds__(256) proj_kernel(
    const float* __restrict__ im_q, const float* __restrict__ im_k,
    const float* __restrict__ W_q,  const float* __restrict__ W_k) {
    const int z  = blockIdx.z;
    const int ks = blockIdx.y;
    const int n0 = blockIdx.x * 16;
    const float* __restrict__ A = z ? im_k : im_q;
    const float* __restrict__ W = z ? W_k  : W_q;

    __shared__ float As[16][32];
    __shared__ float Bs[32][128];

    float acc[2][4] = {{0.f,0.f,0.f,0.f},{0.f,0.f,0.f,0.f}};
    const int t  = threadIdx.x;
    const int r0 = (t >> 5) << 1;
    const int c0 = (t & 31) << 2;
    const int kbeg = ks * 512;

    for (int kb = 0; kb < 512; kb += 32) {
        const int kbase = kbeg + kb;
        {
            int idx = t;
            #pragma unroll
            for (int i = 0; i < 2; ++i) {
                int r = idx >> 5, c = idx & 31;
                As[r][c] = A[(size_t)(n0 + r) * D_IN + kbase + c];
                idx += 256;
            }
        }
        #pragma unroll
        for (int i = 0; i < 16; ++i) {
            int idx = t + i * 256;
            int r = idx >> 7, c = idx & 127;
            Bs[r][c] = W[(size_t)(kbase + r) * DIM + c];
        }
        __syncthreads();
        #pragma unroll
        for (int kc = 0; kc < 32; ++kc) {
            float a0 = As[r0][kc], a1 = As[r0 + 1][kc];
            float4 b = *(const float4*)&Bs[kc][c0];
            acc[0][0] += a0 * b.x; acc[0][1] += a0 * b.y;
            acc[0][2] += a0 * b.z; acc[0][3] += a0 * b.w;
            acc[1][0] += a1 * b.x; acc[1][1] += a1 * b.y;
            acc[1][2] += a1 * b.z; acc[1][3] += a1 * b.w;
        }
        __syncthreads();
    }
    float* P = g_part + ((size_t)(z * 4 + ks) * N_ROWS + n0) * DIM;
    #pragma unroll
    for (int rr = 0; rr < 2; ++rr)
        #pragma unroll
        for (int cc = 0; cc < 4; ++cc)
            P[(size_t)(r0 + rr) * DIM + c0 + cc] = acc[rr][cc];
}

// ================= norm + l_pos + routing =================
__device__ __forceinline__ float block_reduce_128(float v, volatile float* sbuf) {
    #pragma unroll
    for (int o = 16; o > 0; o >>= 1)
        v += __shfl_xor_sync(0xffffffffu, v, o);
    __syncthreads();
    if ((threadIdx.x & 31) == 0) sbuf[threadIdx.x >> 5] = v;
    __syncthreads();
    return sbuf[0] + sbuf[1] + sbuf[2] + sbuf[3];
}

__global__ void __launch_bounds__(128) norm_kernel(const int* __restrict__ label,
                                                   float* __restrict__ out) {
    const int n = blockIdx.x;
    const int j = threadIdx.x;
    __shared__ float sbuf[4];

    float qv = 0.f, kv = 0.f;
    #pragma unroll
    for (int s = 0; s < 4; ++s) {
        qv += g_part[((size_t)s       * N_ROWS + n) * DIM + j];
        kv += g_part[((size_t)(4 + s) * N_ROWS + n) * DIM + j];
    }
    float sq = block_reduce_128(qv * qv, sbuf);
    float sk = block_reduce_128(kv * kv, sbuf);
    float qn = qv / fmaxf(sqrtf(sq), 1e-12f);
    float kn = kv / fmaxf(sqrtf(sk), 1e-12f);
    float lp = block_reduce_128(qn * kn, sbuf);

    float qscaled = qn * INV_T;
    uint32_t qt;
    asm("cvt.rna.tf32.f32 %0, %1;" : "=r"(qt) : "f"(qscaled));
    g_q[(size_t)n * DIM + j] = __uint_as_float(qt);

    if (j == 0) {
        out[(size_t)n * (KNEG + 1)] = lp * INV_T;
        int lab = label[n];
        int gq = ((lab - 1) % NG + NG) % NG;
        int p = atomicAdd(&g_cnt[gq], 1);
        g_rows[gq * N_ROWS + p] = n;
    }
}

// ================= l_neg: tf32 mma.sync + cp.async.bulk (UBLKCP) ring =======
// SMEM: [0..512) rowidx | [512..536) 3 mbars | [1024..68608) A[128][132]
//       [68608..+3*8704) B ring: 3 chunks x [16 feat][136 floats]
#define OFF_ROWIDX 0
#define OFF_MBAR   512
#define OFF_A      1024
#define PA         132
#define OFF_B      (OFF_A + 128 * PA * 4)          // 68608
#define PB         136
#define CHUNK_C    16
#define RING       3
#define CHUNK_BYTES (CHUNK_C * PB * 4)             // 8704
#define CHUNK_TX   (CHUNK_C * 128 * 4)             // 8192 bytes of payload
#define SMEM_LNEG  (OFF_B + RING * CHUNK_BYTES)    // 94720 -> 2 CTA/SM
#define NSTEP      (KT * 8)                         // 32 chunks per CTA

__device__ __forceinline__ uint32_t smem_u32(const void* p) {
    uint32_t a;
    asm("{ .reg .u64 t; cvta.to.shared.u64 t, %1; cvt.u32.u64 %0, t; }" : "=r"(a) : "l"(p));
    return a;
}
__device__ __forceinline__ void mma_tf32(float* c, const uint32_t* a, const uint32_t* b) {
    asm volatile("mma.sync.aligned.m16n8k8.row.col.f32.tf32.tf32.f32 "
        "{%0,%1,%2,%3}, {%4,%5,%6,%7}, {%8,%9}, {%0,%1,%2,%3};"
        : "+f"(c[0]),"+f"(c[1]),"+f"(c[2]),"+f"(c[3])
        : "r"(a[0]),"r"(a[1]),"r"(a[2]),"r"(a[3]), "r"(b[0]),"r"(b[1]));
}
__device__ __forceinline__ void mbar_init(uint32_t mbar, uint32_t cnt) {
    asm volatile("mbarrier.init.shared.b64 [%0], %1;" :: "r"(mbar), "r"(cnt) : "memory");
}
__device__ __forceinline__ void mbar_expect_tx(uint32_t mbar, uint32_t bytes) {
    asm volatile("mbarrier.arrive.expect_tx.shared.b64 _, [%0], %1;"
                 :: "r"(mbar), "r"(bytes) : "memory");
}
__device__ __forceinline__ void mbar_wait(uint32_t mbar, uint32_t parity) {
    uint32_t done;
    asm volatile("{\n\t.reg .pred p;\n\t"
        "mbarrier.try_wait.parity.acquire.cta.shared::cta.b64 p, [%1], %2;\n\t"
        "selp.b32 %0, 1, 0, p;\n\t}"
        : "=r"(done) : "r"(mbar), "r"(parity) : "memory");
    if (!done) {
        asm volatile("{\n\t.reg .pred P1;\n\t"
            "WL_%=:\n\t"
            "mbarrier.try_wait.parity.acquire.cta.shared::cta.b64 P1, [%0], %1, 0x989680;\n\t"
            "@P1 bra.uni WD_%=;\n\t"
            "bra.uni WL_%=;\n\t"
            "WD_%=:\n\t}"
            :: "r"(mbar), "r"(parity) : "memory");
    }
}
__device__ __forceinline__ void bulk_cp(uint32_t dst, const void* src, uint32_t bytes,
                                        uint32_t mbar) {
    asm volatile("cp.async.bulk.shared::cluster.global.mbarrier::complete_tx::bytes "
                 "[%0], [%1], %2, [%3];"
                 :: "r"(dst), "l"(src), "r"(bytes), "r"(mbar) : "memory");
}

// issue chunk cc: 16 rows x 512B; warp w copies rows {w, w+8}; tid0 posts expect_tx
__device__ __forceinline__ void issue_chunk(uint32_t sbase, const float* qgrp,
                                            int kbase_cta, int cc, int w, int lane,
                                            int tid) {
    const int slot = cc % RING;
    const uint32_t mbar = sbase + OFF_MBAR + slot * 8;
    if (tid == 0) mbar_expect_tx(mbar, CHUNK_TX);
    if (lane == 0) {
        const int kt = cc >> 3;
        const int j  = cc & 7;
        const int k0 = kbase_cta + kt * 128;
        const uint32_t dstb = sbase + OFF_B + (uint32_t)slot * CHUNK_BYTES;
        #pragma unroll
        for (int h = 0; h < 2; ++h) {
            int r = w + h * 8;                 // chunk row 0..15
            bulk_cp(dstb + (uint32_t)(r * (PB * 4)),
                    qgrp + (size_t)(j * CHUNK_C + r) * KNEG + k0,
                    512, mbar);
        }
    }
}

__global__ void __launch_bounds__(256, 2) lneg_kernel(const float* __restrict__ queues,
                                                      float* __restrict__ out) {
    const int g   = blockIdx.y;
    const int m0  = blockIdx.z * 128;
    const int cnt = g_cnt[g];
    if (m0 >= cnt) return;

    extern __shared__ char smem[];
    const uint32_t sbase = smem_u32(smem);
    int* rowidx = (int*)(smem + OFF_ROWIDX);
    float* As   = (float*)(smem + OFF_A);

    const int tid  = threadIdx.x;
    const int w    = tid >> 5;
    const int lane = tid & 31;
    const float* qgrp = queues + (size_t)g * DIM * KNEG;
    const int kbase_cta = blockIdx.x * KT * 128;

    if (tid == 0) {
        #pragma unroll
        for (int s = 0; s < RING; ++s) mbar_init(sbase + OFF_MBAR + s * 8, 1);
    }

    // rowidx + A fill (threads 0..127, one gathered q row each)
    if (tid < 128) {
        int r = m0 + tid;
        int myrow = (r < cnt) ? g_rows[g * N_ROWS + r] : -1;
        rowidx[tid] = myrow;
        float* arow = As + tid * PA;
        if (myrow >= 0) {
            const float4* src = (const float4*)(g_q + (size_t)myrow * DIM);
            #pragma unroll
            for (int i = 0; i < 32; ++i)
                *(float4*)(arow + i * 4) = src[i];
        } else {
            #pragma unroll
            for (int i = 0; i < 32; ++i)
                *(float4*)(arow + i * 4) = make_float4(0.f, 0.f, 0.f, 0.f);
        }
    }
    __syncthreads();    // mbars initialized + rowidx/A visible

    // prologue: chunks 0,1 in flight
    issue_chunk(sbase, qgrp, kbase_cta, 0, w, lane, tid);
    issue_chunk(sbase, qgrp, kbase_cta, 1, w, lane, tid);

    const int  m_base  = (w >> 1) * 32;    // warp's 32 rows
    const int  n_basew = (w & 1) * 64;     // warp's 64 cols
    const bool active  = (m0 + m_base) < cnt;

    const int arow0 = m_base + (lane >> 2);
    const int acol0 = lane & 3;
    const int bn0   = n_basew + (lane >> 2);
    const int bk0   = lane & 3;

    float acc[2][8][4];

    for (int cc = 0; cc < NSTEP; ++cc) {
        // issue chunk cc+2 into slot (cc+2)%3 == slot of cc-1 (consumed, synced)
        if (cc + 2 < NSTEP)
            issue_chunk(sbase, qgrp, kbase_cta, cc + 2, w, lane, tid);

        // wait for chunk cc (use index cc/RING -> parity)
        mbar_wait(sbase + OFF_MBAR + (cc % RING) * 8, (uint32_t)((cc / RING) & 1));

        if (active) {
            if ((cc & 7) == 0) {
                #pragma unroll
                for (int mi = 0; mi < 2; ++mi)
                    #pragma unroll
                    for (int ni = 0; ni < 8; ++ni)
                        #pragma unroll
                        for (int e = 0; e < 4; ++e) acc[mi][ni][e] = 0.f;
            }

            const float* chunk = (const float*)(smem + OFF_B +
                                 (uint32_t)(cc % RING) * CHUNK_BYTES);
            const int cbase = (cc & 7) * CHUNK_C;

            #pragma unroll
            for (int ks2 = 0; ks2 < 2; ++ks2) {
                const int kloc = ks2 * 8;
                uint32_t a[2][4];
                #pragma unroll
                for (int mi = 0; mi < 2; ++mi) {
                    const float* ap = As + (arow0 + mi * 16) * PA + cbase + kloc + acol0;
                    a[mi][0] = __float_as_uint(ap[0]);
                    a[mi][1] = __float_as_uint(ap[8 * PA]);
                    a[mi][2] = __float_as_uint(ap[4]);
                    a[mi][3] = __float_as_uint(ap[8 * PA + 4]);
                }
                #pragma unroll
                for (int ni = 0; ni < 8; ++ni) {
                    const float* bp = chunk + (kloc + bk0) * PB + bn0 + ni * 8;
                    uint32_t b[2];
                    b[0] = __float_as_uint(bp[0]);
                    b[1] = __float_as_uint(bp[4 * PB]);
                    mma_tf32(acc[0][ni], a[0], b);
                    mma_tf32(acc[1][ni], a[1], b);
                }
            }

            // end of k-tile: store
            if ((cc & 7) == 7) {
                const int k0 = kbase_cta + (cc >> 3) * 128;
                #pragma unroll
                for (int mi = 0; mi < 2; ++mi) {
                    int rlo = m_base + mi * 16 + (lane >> 2);
                    int n0r = rowidx[rlo];
                    int n1r = rowidx[rlo + 8];
                    #pragma unroll
                    for (int ni = 0; ni < 8; ++ni) {
                        size_t col = (size_t)(1 + k0 + n_basew + ni * 8 + (lane & 3) * 2);
                        if (n0r >= 0) {
                            float* p0 = out + (size_t)n0r * (KNEG + 1) + col;
                            p0[0] = acc[mi][ni][0];
                            p0[1] = acc[mi][ni][1];
                        }
                        if (n1r >= 0) {
                            float* p1 = out + (size_t)n1r * (KNEG + 1) + col;
                            p1[0] = acc[mi][ni][2];
                            p1[1] = acc[mi][ni][3];
                        }
                    }
                }
            }
        }
        __syncthreads();   // all reads of slot cc done before its reuse at cc+3
    }
}

// ================= launch =================
extern "C" void kernel_launch(void* const* d_in, const int* in_sizes, int n_in,
                              void* d_out, int out_size) {
    const float* im_q   = (const float*)d_in[0];
    const float* im_k   = (const float*)d_in[1];
    const float* W_q    = (const float*)d_in[2];
    const float* W_k    = (const float*)d_in[3];
    const float* queues = (const float*)d_in[4];
    const int*   label  = (const int*)d_in[5];
    float* out = (float*)d_out;

    cudaFuncSetAttribute(lneg_kernel, cudaFuncAttributeMaxDynamicSharedMemorySize, SMEM_LNEG);

    init_kernel<<<1, 256>>>(out, (long long)out_size);
    proj_kernel<<<dim3(32, 4, 2), 256>>>(im_q, im_k, W_q, W_k);
    norm_kernel<<<N_ROWS, 128>>>(label, out);
    lneg_kernel<<<dim3(KNEG / (128 * KT), NG, 4), 256, SMEM_LNEG>>>(queues, out);
}